// round 12
// baseline (speedup 1.0000x reference)
#include <cuda_runtime.h>
#include <cstdint>

// Problem constants (upper bounds; runtime shapes read from in_sizes)
#define NMAX 16384
#define PMAX 4096
#define NB   16384              // rank buckets
#define RMAX (NMAX + PMAX)      // 20480 distinct ranks max

typedef unsigned int u32;
typedef unsigned short u16;

// -------- cross-kernel scratch (allocation-free: __device__ globals) --------
__device__ u16 g_writer[PMAX];        // last writer item per slot, 0xFFFF = keep original
__device__ u32 g_hist[RMAX];          // pool-rank histogram (written by k_prep)
__device__ u32 g_cursor[RMAX];        // psBelow (k_prep) -> U cursors (k_resolve)
__device__ u32 g_bdata[RMAX];         // accepted list (k_resolve accept phase)
__device__ u16 g_rank_scores[NMAX];   // exact rank of each score
__device__ u16 g_rank_prior[PMAX];    // exact rank of each input priority
__device__ u16 g_sr[NMAX];            // stream ranks
__device__ u16 g_si[NMAX];            // stream item ids
__device__ u16 g_chunkS[NMAX];        // per-256-chunk sorted stream ranks
__device__ u16 g_psr[PMAX];           // poolstart ranks
__device__ u32 g_Bq[NMAX];            // dominance counts
__device__ int g_T, g_fc;

// order-preserving u32 transform of float (total order matching IEEE <)
__device__ __forceinline__ u32 okey(float v) {
    u32 b = __float_as_uint(v);
    return (b & 0x80000000u) ? ~b : (b | 0x80000000u);
}
// monotone bucketing (exactness NOT required; monotone + equal-on-equal is)
__device__ __forceinline__ int bucketOf(float v) {
    if (!(v > 0.0f)) return 0;
    if (v >= 1.0f)   return NB - 1;
    int b = (int)(v * 16384.0f);
    return b < 0 ? 0 : (b > NB - 1 ? NB - 1 : b);
}

// ---- k_prep smem layout (u32 words) ----
// hist  [0, 16384)        : bucket hist -> exclusive prefix (in place); later chunkS alias
// cur   [16384, 32768)    : prefix copy -> scatter cursors (end ptrs); later staged scores
// bdata [32768, 53248)    : okeys grouped by bucket; later pool-rank histogram (RMAX)
// wr    [53248, 55296)    : u16[4096] writer map
#define PREP_WORDS 55296      // 221,184 bytes

// ---------------------------------------------------------------------------
// k_prep (single block): ENTIRE front end.
//  rank pipeline (hist/scan/scatter/rank) in smem -> g_rank_scores/g_rank_prior
//  classify -> wr appends + g_si stream; stream ranks -> g_sr
//  pool ranks -> g_psr, g_writer; pool hist -> g_hist; psBelow -> g_cursor
//  per-256-chunk bitonic sort of stream ranks -> g_chunkS
// ---------------------------------------------------------------------------
__global__ __launch_bounds__(1024, 1)
void k_prep(const float* __restrict__ scores,
            const float* __restrict__ priorities,
            const int* __restrict__ countp,
            int N, int P) {
    extern __shared__ u32 S[];
    u32* hist  = S;                       // NB
    u32* cur   = S + NB;                  // NB
    u32* bdata = S + 2 * NB;              // RMAX
    u16* wr    = (u16*)(S + 2 * NB + RMAX); // PMAX
    u32* sbits = cur;                     // alias after rank step
    u16* chunkS = (u16*)hist;             // alias after rank step
    u32* phist = bdata;                   // alias after rank step (RMAX)
    __shared__ int wsum[32];

    const int tid = threadIdx.x;
    const int nthr = blockDim.x;
    const int lane = tid & 31, wid = tid >> 5;
    const int M = N + P;

    // ---- 1. zero hist ----
    for (int i = tid; i < NB; i += nthr) hist[i] = 0u;
    for (int i = tid; i < PMAX; i += nthr) wr[i] = 0xFFFFu;
    __syncthreads();

    // ---- 2. bucket histogram ----
    for (int i = tid; i < M; i += nthr) {
        float v = (i < N) ? scores[i] : priorities[i - N];
        atomicAdd(&hist[bucketOf(v)], 1u);
    }
    __syncthreads();

    // ---- 3. exclusive prefix (in place) + cursor copy ----
    {
        const int CPT = NB / 1024;        // 16
        const int base = tid * CPT;
        u32 s = 0;
        #pragma unroll
        for (int j = 0; j < CPT; ++j) s += hist[base + j];
        u32 v = s;
        #pragma unroll
        for (int o = 1; o < 32; o <<= 1) {
            u32 t = __shfl_up_sync(0xFFFFFFFFu, v, o);
            if (lane >= o) v += t;
        }
        if (lane == 31) wsum[wid] = (int)v;
        __syncthreads();
        if (wid == 0) {
            u32 w = (u32)wsum[lane];
            #pragma unroll
            for (int o = 1; o < 32; o <<= 1) {
                u32 t = __shfl_up_sync(0xFFFFFFFFu, w, o);
                if (lane >= o) w += t;
            }
            wsum[lane] = (int)w;
        }
        __syncthreads();
        u32 run = (v - s) + ((wid > 0) ? (u32)wsum[wid - 1] : 0u);
        #pragma unroll
        for (int j = 0; j < CPT; ++j) {
            u32 h = hist[base + j];
            hist[base + j] = run;
            cur[base + j] = run;
            run += h;
        }
        __syncthreads();
    }

    // ---- 4. scatter okeys by bucket ----
    for (int i = tid; i < M; i += nthr) {
        float v = (i < N) ? scores[i] : priorities[i - N];
        u32 pos = atomicAdd(&cur[bucketOf(v)], 1u);
        bdata[pos] = okey(v);
    }
    __syncthreads();
    // now: hist[b] = bucket start, cur[b] = bucket end

    // ---- 5. exact ranks ----
    for (int i = tid; i < M; i += nthr) {
        float v = (i < N) ? scores[i] : priorities[i - N];
        u16 r;
        if (!(v > 0.0f)) {
            r = 0;   // no negative candidates -> rank(<=0)=0
        } else {
            int b = bucketOf(v);
            u32 k = okey(v);
            u32 s0 = hist[b], e0 = cur[b];
            u32 c = 0;
            for (u32 j = s0; j < e0; ++j) c += (bdata[j] < k) ? 1u : 0u;
            r = (u16)(s0 + c);
        }
        if (i < N) g_rank_scores[i] = r; else g_rank_prior[i - N] = r;
    }
    __syncthreads();
    // hist/cur/bdata contents now dead -> aliases live

    // ---- 6. stage scores into sbits (cur region), classify ----
    for (int i4 = tid; i4 < NMAX / 4; i4 += nthr) {
        int i = i4 * 4;
        uint4 v;
        if (i + 3 < N) {
            v = *reinterpret_cast<const uint4*>(scores + i);
        } else {
            v.x = (i + 0 < N) ? __float_as_uint(scores[i + 0]) : 0u;
            v.y = (i + 1 < N) ? __float_as_uint(scores[i + 1]) : 0u;
            v.z = (i + 2 < N) ? __float_as_uint(scores[i + 2]) : 0u;
            v.w = (i + 3 < N) ? __float_as_uint(scores[i + 3]) : 0u;
        }
        *reinterpret_cast<uint4*>(sbits + i) = v;
    }
    __syncthreads();

    const int C0 = *countp;
    const int CH = NMAX / 1024;            // 16
    const int start = tid * CH;
    int c = 0;
    #pragma unroll
    for (int j = 0; j < CH; ++j)
        c += (__uint_as_float(sbits[start + j]) > 0.5f) ? 1 : 0;

    int v = c;
    #pragma unroll
    for (int o = 1; o < 32; o <<= 1) {
        int t = __shfl_up_sync(0xFFFFFFFFu, v, o);
        if (lane >= o) v += t;
    }
    if (lane == 31) wsum[wid] = v;
    __syncthreads();
    if (wid == 0) {
        int w = wsum[lane];
        #pragma unroll
        for (int o = 1; o < 32; o <<= 1) {
            int t = __shfl_up_sync(0xFFFFFFFFu, w, o);
            if (lane >= o) w += t;
        }
        wsum[lane] = w;
    }
    __syncthreads();
    const int excl = (v - c) + ((wid > 0) ? wsum[wid - 1] : 0);
    const int total = wsum[(nthr >> 5) - 1];
    int room = P - C0; if (room < 0) room = 0;
    const int T  = (total > room) ? total - room : 0;
    const int fc = C0 + ((total < room) ? total : room);
    {
        int r = excl;
        #pragma unroll
        for (int j = 0; j < CH; ++j) {
            int i = start + j;
            if (__uint_as_float(sbits[i]) > 0.5f) {
                if (r < room) wr[C0 + r] = (u16)i;
                else          g_si[r - room] = (u16)i;
                r++;
            }
        }
    }
    if (tid == 0) { g_T = T; g_fc = fc; }
    __syncthreads();

    // ---- 7. stream ranks ----
    for (int q = tid; q < T; q += nthr) g_sr[q] = g_rank_scores[g_si[q]];

    // ---- 8. pool ranks + pool hist (phist = bdata alias) + psBelow ----
    for (int i = tid; i < RMAX; i += nthr) phist[i] = 0u;
    __syncthreads();
    for (int i = tid; i < P; i += nthr) {
        u16 w = wr[i];
        u16 pr = (w != 0xFFFFu) ? g_rank_scores[w] : g_rank_prior[i];
        g_psr[i] = pr;
        g_writer[i] = w;
        atomicAdd(&phist[pr], 1u);
    }
    __syncthreads();
    {   // exclusive prefix over RMAX -> g_cursor (psBelow); also dump hist -> g_hist
        const int CPT = RMAX / 1024;       // 20
        const int base = tid * CPT;
        u32 s = 0;
        #pragma unroll
        for (int j = 0; j < CPT; ++j) s += phist[base + j];
        u32 vv = s;
        #pragma unroll
        for (int o = 1; o < 32; o <<= 1) {
            u32 t = __shfl_up_sync(0xFFFFFFFFu, vv, o);
            if (lane >= o) vv += t;
        }
        if (lane == 31) wsum[wid] = (int)vv;
        __syncthreads();
        if (wid == 0) {
            u32 w = (u32)wsum[lane];
            #pragma unroll
            for (int o = 1; o < 32; o <<= 1) {
                u32 t = __shfl_up_sync(0xFFFFFFFFu, w, o);
                if (lane >= o) w += t;
            }
            wsum[lane] = (int)w;
        }
        __syncthreads();
        u32 run = (vv - s) + ((wid > 0) ? (u32)wsum[wid - 1] : 0u);
        #pragma unroll
        for (int j = 0; j < CPT; ++j) {
            u32 h = phist[base + j];
            g_hist[base + j] = h;
            g_cursor[base + j] = run;
            run += h;
        }
    }
    __syncthreads();

    // ---- 9. per-256-chunk bitonic sorts (chunkS = hist alias) ----
    {
        const int NCH = NMAX / 256;        // 64 chunks (pad beyond T with 0xFFFF)
        for (int i = tid; i < NMAX; i += nthr)
            chunkS[i] = (i < T) ? g_sr[i] : (u16)0xFFFFu;
        __syncthreads();
        for (int ch = wid; ch < NCH; ch += 32) {
            u16* a = chunkS + (ch << 8);
            for (int k = 2; k <= 256; k <<= 1) {
                for (int j = k >> 1; j > 0; j >>= 1) {
                    for (int idx = lane; idx < 256; idx += 32) {
                        int p = idx ^ j;
                        if (p > idx) {
                            u16 x = a[idx], y = a[p];
                            bool up = ((idx & k) == 0);
                            if (up ? (x > y) : (x < y)) { a[idx] = y; a[p] = x; }
                        }
                    }
                    __syncwarp();
                }
            }
        }
        __syncthreads();
        for (int i = tid; i < NMAX; i += nthr) g_chunkS[i] = chunkS[i];
    }
}

// ---------------------------------------------------------------------------
// k_count: grid-wide dominance counts. One warp per stream item:
//   B(q) = sum over full chunks < chunk(q) of lb(chunkS, r_q)
//        + #{j in same chunk, j<q : r_j < r_q}
// ---------------------------------------------------------------------------
__global__ __launch_bounds__(256, 8)
void k_count() {
    const int T = g_T;
    if (T <= 0) return;
    const int lane = threadIdx.x & 31;
    const int warpsTotal = (gridDim.x * blockDim.x) >> 5;
    const int gw = ((blockIdx.x * blockDim.x + threadIdx.x) >> 5);

    for (int q = gw; q < T; q += warpsTotal) {
        const u16 r = g_sr[q];
        const int c0 = q >> 8;
        u32 cnt = 0;
        for (int ch = lane; ch < c0; ch += 32) {
            const u16* a = g_chunkS + (ch << 8);
            int lo = 0, hi = 256;
            while (lo < hi) { int m = (lo + hi) >> 1; if (a[m] < r) lo = m + 1; else hi = m; }
            cnt += (u32)lo;
        }
        for (int j = (q & ~255) + lane; j < q; j += 32)
            cnt += (g_sr[j] < r) ? 1u : 0u;
        #pragma unroll
        for (int o = 16; o; o >>= 1) cnt += __shfl_down_sync(0xFFFFFFFFu, cnt, o);
        if (lane == 0) g_Bq[q] = cnt;
    }
}

// ---------------------------------------------------------------------------
// k_resolve (single block): FUSED accept + resolve + epilogue.
//  accept(q) <=> psBelow[r_q] + B(q) >= q+1 ; ordered compaction -> g_bdata.
//  Then: counting sort of U = poolstart ∪ accepted by rank into smem gU;
//  accept j evicts gU[j]; slot chains via early-exit pointer jumping; intra-
//  rank tie fixpoint by slot; survivors -> writer map; epilogue.
// ---------------------------------------------------------------------------
__global__ __launch_bounds__(1024, 1)
void k_resolve(const float* __restrict__ scores,
               const float* __restrict__ priorities,
               float* __restrict__ out,
               int P, int D, long long out_size) {
    extern __shared__ u32 S[];
    u32* gU  = S;                          // RMAX
    u32* par = S + RMAX;                   // NMAX
    u16* wr  = (u16*)(S + RMAX + NMAX);    // PMAX
    __shared__ int wsum[32];
    __shared__ int sh_changed, sh_anyTies, sh_A;

    const int tid = threadIdx.x;
    const int nthr = blockDim.x;
    const int lane = tid & 31, wid = tid >> 5;
    const int T = g_T;

    // ---- accept phase ----
    {
        int myCnt = 0;
        u32 amask = 0;
        const int q0 = tid * 16;
        u16 rs[16];
        #pragma unroll
        for (int j = 0; j < 16; ++j) {
            int q = q0 + j;
            if (q < T) {
                u16 r = g_sr[q];
                rs[j] = r;
                int b = (int)g_Bq[q];
                int psb = (int)g_cursor[r];
                if (psb + b >= q + 1) { amask |= (1u << j); myCnt++; }
            }
        }
        int vv = myCnt;
        #pragma unroll
        for (int o = 1; o < 32; o <<= 1) {
            int t = __shfl_up_sync(0xFFFFFFFFu, vv, o);
            if (lane >= o) vv += t;
        }
        if (lane == 31) wsum[wid] = vv;
        __syncthreads();
        if (wid == 0) {
            int w = wsum[lane];
            #pragma unroll
            for (int o = 1; o < 32; o <<= 1) {
                int t = __shfl_up_sync(0xFFFFFFFFu, w, o);
                if (lane >= o) w += t;
            }
            wsum[lane] = w;
        }
        __syncthreads();
        int jbase = (vv - myCnt) + ((wid > 0) ? wsum[wid - 1] : 0);
        if (tid == 0) sh_A = wsum[(nthr >> 5) - 1];
        #pragma unroll
        for (int j = 0; j < 16; ++j) {
            if (amask & (1u << j)) {
                int q = q0 + j;
                g_bdata[jbase++] = ((u32)rs[j] << 14) | (u32)g_si[q];
            }
        }
        __syncthreads();
    }
    const int A = sh_A;

    for (int i = tid; i < PMAX; i += nthr) wr[i] = (i < P) ? g_writer[i] : (u16)0xFFFFu;
    __syncthreads();

    if (A > 0) {
        const int UN = P + A;

        // add accepted ranks to the pool histogram
        for (int j = tid; j < A; j += nthr) atomicAdd(&g_hist[g_bdata[j] >> 14], 1u);
        __syncthreads();
        {   // exclusive prefix over RMAX -> g_cursor (U cursors)
            const int CPT = RMAX / 1024;
            const int base = tid * CPT;
            u32 s = 0;
            #pragma unroll
            for (int j = 0; j < CPT; ++j) s += g_hist[base + j];
            u32 vv = s;
            #pragma unroll
            for (int o = 1; o < 32; o <<= 1) {
                u32 t = __shfl_up_sync(0xFFFFFFFFu, vv, o);
                if (lane >= o) vv += t;
            }
            if (lane == 31) wsum[wid] = (int)vv;
            __syncthreads();
            if (wid == 0) {
                u32 w = (u32)wsum[lane];
                #pragma unroll
                for (int o = 1; o < 32; o <<= 1) {
                    u32 t = __shfl_up_sync(0xFFFFFFFFu, w, o);
                    if (lane >= o) w += t;
                }
                wsum[lane] = (int)w;
            }
            __syncthreads();
            u32 run = (vv - s) + ((wid > 0) ? (u32)wsum[wid - 1] : 0u);
            #pragma unroll
            for (int j = 0; j < CPT; ++j) {
                u32 h = g_hist[base + j];
                g_cursor[base + j] = run;
                run += h;
            }
            __syncthreads();
        }
        // scatter: elem = rank<<17 | type<<16 | id
        for (int i = tid; i < P; i += nthr) {
            u32 r = (u32)g_psr[i];
            u32 pos = atomicAdd(&g_cursor[r], 1u);
            gU[pos] = (r << 17) | (u32)i;
        }
        for (int j = tid; j < A; j += nthr) {
            u32 r = g_bdata[j] >> 14;
            u32 pos = atomicAdd(&g_cursor[r], 1u);
            gU[pos] = (r << 17) | 0x10000u | (u32)j;
        }
        __syncthreads();

        // tie detection
        if (tid == 0) sh_anyTies = 0;
        __syncthreads();
        for (int p = tid; p + 1 < UN; p += nthr)
            if ((gU[p] >> 17) == (gU[p + 1] >> 17)) sh_anyTies = 1;
        __syncthreads();

        const int MAXIT = 32;
        for (int it = 0; it < MAXIT; ++it) {
            for (int j = tid; j < A; j += nthr) {
                u32 e = gU[j];
                par[j] = (e & 0x10000u) ? (e & 0xFFFFu) : (0x80000000u | (e & 0xFFFFu));
            }
            __syncthreads();
            for (int rd = 0; rd < 15; ++rd) {
                if (tid == 0) sh_changed = 0;
                __syncthreads();
                for (int j = tid; j < A; j += nthr) {
                    u32 pv = par[j];
                    if (!(pv & 0x80000000u)) {
                        u32 g = par[pv];
                        par[j] = g;
                        if (!(g & 0x80000000u)) sh_changed = 1;
                    }
                }
                __syncthreads();
                if (!sh_changed) break;
            }
            if (!sh_anyTies) break;
            if (it == MAXIT - 1) break;
            if (tid == 0) sh_changed = 0;
            __syncthreads();
            for (int p = tid; p < UN; p += nthr) {
                u32 r = gU[p] >> 17;
                bool leader = (p == 0) || ((gU[p - 1] >> 17) != r);
                if (leader && p + 1 < UN && (gU[p + 1] >> 17) == r) {
                    int len = 1;
                    while (p + len < UN && (gU[p + len] >> 17) == r) len++;
                    bool ch = false;
                    for (int a = 1; a < len; ++a) {
                        u32 x = gU[p + a];
                        u32 sx = (x & 0x10000u) ? (par[x & 0xFFFFu] & 0xFFFFu) : (x & 0xFFFFu);
                        u32 kx = (sx << 1) | ((x >> 16) & 1u);
                        int b = a;
                        while (b > 0) {
                            u32 y = gU[p + b - 1];
                            u32 sy = (y & 0x10000u) ? (par[y & 0xFFFFu] & 0xFFFFu) : (y & 0xFFFFu);
                            u32 ky = (sy << 1) | ((y >> 16) & 1u);
                            if (ky <= kx) break;
                            gU[p + b] = y; b--; ch = true;
                        }
                        gU[p + b] = x;
                    }
                    if (ch) sh_changed = 1;
                }
            }
            __syncthreads();
            if (!sh_changed) break;
        }

        // survivors (positions >= A) write the final map
        for (int pos = A + tid; pos < UN; pos += nthr) {
            u32 e = gU[pos];
            if (e & 0x10000u) {
                u32 j = e & 0xFFFFu;
                u32 s = par[j] & 0xFFFFu;
                if (s < (u32)P) wr[s] = (u16)(g_bdata[j] & 0x3FFFu);
            }
        }
        __syncthreads();
    }

    // epilogue
    const long long obase = (long long)P * (long long)D;
    for (int i = tid; i < P; i += nthr) {
        u16 w = wr[i];
        g_writer[i] = w;
        if (obase + i < out_size)
            out[obase + i] = (w != 0xFFFFu) ? scores[w] : priorities[i];
    }
    if (tid == 0 && obase + P < out_size)
        out[obase + P] = (float)g_fc;
}

// ---------------------------------------------------------------------------
// Row gather: one block per pool slot.
// ---------------------------------------------------------------------------
__global__ void k_copy(const float* __restrict__ pool,
                       const float* __restrict__ summaries,
                       float* __restrict__ out, int D) {
    const int row = blockIdx.x;
    const u16 w = g_writer[row];
    const float* src = (w == 0xFFFFu) ? (pool + (long long)row * D)
                                      : (summaries + (long long)w * D);
    float* dst = out + (long long)row * D;
    if ((D & 3) == 0) {
        const float4* s4 = (const float4*)src;
        float4* d4 = (float4*)dst;
        for (int i = threadIdx.x; i < (D >> 2); i += blockDim.x) d4[i] = s4[i];
    } else {
        for (int i = threadIdx.x; i < D; i += blockDim.x) dst[i] = src[i];
    }
}

// ---------------------------------------------------------------------------
// Inputs (metadata order): summaries[N,D] f32, scores[N] f32, pool[P,D] f32,
// priorities[P] f32, count i32 scalar.
// Output: concat(pool_out[P*D], priorities[P], count) as f32.
// ---------------------------------------------------------------------------
extern "C" void kernel_launch(void* const* d_in, const int* in_sizes, int n_in,
                              void* d_out, int out_size) {
    const float* summaries  = (const float*)d_in[0];
    const float* scores     = (const float*)d_in[1];
    const float* pool       = (const float*)d_in[2];
    const float* priorities = (const float*)d_in[3];
    const int*   countp     = (const int*)d_in[4];

    const int N = in_sizes[1];
    const int P = in_sizes[3];
    const int D = (N > 0) ? (in_sizes[0] / N) : 0;
    float* out = (float*)d_out;

    const int prep_smem = PREP_WORDS * 4;                // 221,184
    const int res_smem  = (RMAX + NMAX) * 4 + PMAX * 2;  // 155,648
    cudaFuncSetAttribute(k_prep,    cudaFuncAttributeMaxDynamicSharedMemorySize, prep_smem);
    cudaFuncSetAttribute(k_resolve, cudaFuncAttributeMaxDynamicSharedMemorySize, res_smem);

    k_prep   <<<1, 1024, prep_smem>>>(scores, priorities, countp, N, P);
    k_count  <<<512, 256>>>();
    k_resolve<<<1, 1024, res_smem>>>(scores, priorities, out, P, D, (long long)out_size);
    k_copy   <<<P, 256>>>(pool, summaries, out, D);
}

// round 13
// speedup vs baseline: 1.7582x; 1.7582x over previous
#include <cuda_runtime.h>
#include <cstdint>

// Problem constants (upper bounds; runtime shapes read from in_sizes)
#define NMAX 16384
#define PMAX 4096
#define NB   16384              // rank buckets
#define RMAX (NMAX + PMAX)      // 20480 distinct ranks max

#define G_BLOCKS 128
#define B_THREADS 512

typedef unsigned int u32;
typedef unsigned short u16;

// -------- cross-kernel scratch (allocation-free: __device__ globals) --------
__device__ u16 g_writer[PMAX];        // last writer item per slot, 0xFFFF = keep original
__device__ u32 g_hist[RMAX];          // pool-rank histogram
__device__ u32 g_cursor[RMAX];        // psBelow -> U cursors (k_resolve)
__device__ u32 g_bdata[RMAX];         // okeys by bucket (front) / accepted list (resolve)
__device__ u16 g_rank_scores[NMAX];   // exact rank of each score
__device__ u16 g_rank_prior[PMAX];    // exact rank of each input priority
__device__ u16 g_sr[NMAX];            // stream ranks
__device__ u16 g_si[NMAX];            // stream item ids
__device__ u16 g_chunkS[NMAX];        // per-256-chunk sorted stream ranks
__device__ u16 g_psr[PMAX];           // poolstart ranks
__device__ u32 g_Bq[NMAX];            // dominance counts
__device__ int g_T, g_fc, g_room, g_C0;

// front-end pipeline scratch
__device__ u32 g_bhist[NB];           // bucket histogram
__device__ u32 g_bprefix[NB];         // bucket start
__device__ u32 g_bcur[NB];            // bucket cursor/end
__device__ u32 g_bpart[G_BLOCKS];     // scan partials (buckets)
__device__ u32 g_cpart[G_BLOCKS];     // classify partials
__device__ u32 g_coff[G_BLOCKS];      // classify block offsets
__device__ u32 g_ppart[G_BLOCKS];     // psBelow partials
__device__ u32 g_poff[G_BLOCKS];      // psBelow block offsets

// software grid barrier state (persists across launches; gen is monotonic)
__device__ unsigned int g_barcnt;
__device__ volatile unsigned int g_bargen;

__device__ __forceinline__ void gridbar() {
    __threadfence();
    __syncthreads();
    if (threadIdx.x == 0) {
        unsigned int gen = g_bargen;
        if (atomicAdd(&g_barcnt, 1u) == (unsigned)(G_BLOCKS - 1)) {
            g_barcnt = 0u;
            __threadfence();
            g_bargen = gen + 1u;
        } else {
            while (g_bargen == gen) { __nanosleep(64); }
        }
    }
    __syncthreads();
}

// cross-block coherent loads (bypass non-coherent L1)
__device__ __forceinline__ u32 LDCG32(const u32* p) { return __ldcg(p); }
__device__ __forceinline__ int  LDCGI(const int* p)  { return __ldcg(p); }
__device__ __forceinline__ u16  LDCG16(const u16* p) {
    unsigned short v;
    asm volatile("ld.global.cg.u16 %0, [%1];" : "=h"(v) : "l"(p));
    return v;
}

// order-preserving u32 transform of float (total order matching IEEE <)
__device__ __forceinline__ u32 okey(float v) {
    u32 b = __float_as_uint(v);
    return (b & 0x80000000u) ? ~b : (b | 0x80000000u);
}
// monotone bucketing (exactness NOT required; monotone + equal-on-equal is)
__device__ __forceinline__ int bucketOf(float v) {
    if (!(v > 0.0f)) return 0;
    if (v >= 1.0f)   return NB - 1;
    int b = (int)(v * 16384.0f);
    return b < 0 ? 0 : (b > NB - 1 ? NB - 1 : b);
}

// inclusive block scan over values held by threads tid < NACT (NACT multiple
// of 32). ALL threads must call (contains __syncthreads). wtot gets warp tails.
template<int NACT>
__device__ __forceinline__ u32 blockScanIncl(u32 h, int tid, int lane, int w, u32* wtot) {
    u32 v = h;
    #pragma unroll
    for (int o = 1; o < 32; o <<= 1) {
        u32 x = __shfl_up_sync(0xFFFFFFFFu, v, o);
        if (lane >= o) v += x;
    }
    if (tid < NACT && lane == 31) wtot[w] = v;
    __syncthreads();
    u32 off = 0;
    if (tid < NACT) {
        #pragma unroll
        for (int j = 0; j < NACT / 32; ++j) if (j < w) off += wtot[j];
    }
    return v + off;
}

// ---------------------------------------------------------------------------
// k_front: persistent grid-wide front end (replaces hist/scan/scatter/rank/
// classify/chunksort). Every phase runs at full-chip parallelism; phases are
// separated by software grid barriers. Logic is a 1:1 port of the verified
// R10 kernels.
// ---------------------------------------------------------------------------
__global__ __launch_bounds__(B_THREADS, 1)
void k_front(const float* __restrict__ scores,
             const float* __restrict__ priorities,
             const int* __restrict__ countp,
             int N, int P) {
    __shared__ u32 wtot[16];
    __shared__ u32 wcnt[16];
    __shared__ u16 chunkbuf[256];

    const int tid  = threadIdx.x;
    const int b    = blockIdx.x;
    const int gtid = b * B_THREADS + tid;
    const int lane = tid & 31, w = tid >> 5;
    const int M = N + P;

    // ---- ph0: zero scratch ----
    if (gtid < NB)   g_bhist[gtid]  = 0u;
    if (gtid < RMAX) g_hist[gtid]   = 0u;
    if (gtid < PMAX) g_writer[gtid] = 0xFFFFu;
    gridbar();

    // ---- ph1: bucket histogram ----
    if (gtid < M) {
        float v = (gtid < N) ? scores[gtid] : priorities[gtid - N];
        atomicAdd(&g_bhist[bucketOf(v)], 1u);
    }
    gridbar();

    // ---- ph2a: block-local scan of this block's 128-bucket segment ----
    u32 h2 = 0, incl2 = 0;
    {
        if (tid < 128) h2 = LDCG32(&g_bhist[b * 128 + tid]);
        incl2 = blockScanIncl<128>(h2, tid, lane, w, wtot);
        if (tid == 0) g_bpart[b] = wtot[0] + wtot[1] + wtot[2] + wtot[3];
    }
    gridbar();

    // ---- ph2b: block0 exclusive-scans g_bpart in place ----
    if (b == 0) {
        u32 hB = (tid < 128) ? LDCG32(&g_bpart[tid]) : 0u;
        u32 inclB = blockScanIncl<128>(hB, tid, lane, w, wtot);
        __syncthreads();
        if (tid < 128) g_bpart[tid] = inclB - hB;
    }
    gridbar();

    // ---- ph2c: final bucket prefixes + cursors ----
    if (tid < 128) {
        u32 off = LDCG32(&g_bpart[b]);
        u32 pre = off + (incl2 - h2);
        int idx = b * 128 + tid;
        g_bprefix[idx] = pre;
        g_bcur[idx]    = pre;
    }
    gridbar();

    // ---- ph3: scatter okeys by bucket ----
    if (gtid < M) {
        float v = (gtid < N) ? scores[gtid] : priorities[gtid - N];
        u32 pos = atomicAdd(&g_bcur[bucketOf(v)], 1u);
        g_bdata[pos] = okey(v);
    }
    gridbar();

    // ---- ph4: exact ranks + classify partials ----
    if (gtid < M) {
        float v = (gtid < N) ? scores[gtid] : priorities[gtid - N];
        u16 r;
        if (!(v > 0.0f)) {
            r = 0;   // no negative candidates -> rank(<=0)=0
        } else {
            int bb = bucketOf(v);
            u32 k = okey(v);
            u32 s0 = LDCG32(&g_bprefix[bb]), e0 = LDCG32(&g_bcur[bb]);
            u32 c = 0;
            for (u32 j = s0; j < e0; ++j) c += (LDCG32(&g_bdata[j]) < k) ? 1u : 0u;
            r = (u16)(s0 + c);
        }
        if (gtid < N) g_rank_scores[gtid] = r; else g_rank_prior[gtid - N] = r;
    }
    const bool f = (gtid < N) && (scores[gtid] > 0.5f);
    u32 fmask = __ballot_sync(0xFFFFFFFFu, f);
    const u32 lanepref = __popc(fmask & ((1u << lane) - 1u));
    if (lane == 0) wcnt[w] = __popc(fmask);
    __syncthreads();
    if (tid == 0) {
        u32 tot = 0;
        #pragma unroll
        for (int j = 0; j < 16; ++j) tot += wcnt[j];
        g_cpart[b] = tot;
    }
    gridbar();

    // ---- ph5: block0 scans g_cpart -> g_coff; metas ----
    if (b == 0) {
        u32 hC = (tid < 128) ? LDCG32(&g_cpart[tid]) : 0u;
        u32 inclC = blockScanIncl<128>(hC, tid, lane, w, wtot);
        if (tid < 128) g_coff[tid] = inclC - hC;
        if (tid == 0) {
            int total = (int)(wtot[0] + wtot[1] + wtot[2] + wtot[3]);
            int C0 = *countp;
            int room = P - C0; if (room < 0) room = 0;
            g_T    = (total > room) ? total - room : 0;
            g_fc   = C0 + ((total < room) ? total : room);
            g_room = room;
            g_C0   = C0;
        }
    }
    gridbar();

    // ---- ph6: classify writes (appends + phase-2 stream) ----
    if (f) {
        int room = LDCGI(&g_room);
        int C0   = LDCGI(&g_C0);
        u32 woff = 0;
        #pragma unroll
        for (int j = 0; j < 16; ++j) if (j < w) woff += wcnt[j];   // smem persisted
        int r = (int)(LDCG32(&g_coff[b]) + woff + lanepref);
        if (r < room) g_writer[C0 + r] = (u16)gtid;
        else          g_si[r - room]   = (u16)gtid;
    }
    gridbar();

    // ---- ph7: pool ranks + hist, stream ranks ----
    {
        int T = LDCGI(&g_T);
        if (gtid < P) {
            u16 wv = LDCG16(&g_writer[gtid]);
            u16 pr = (wv != 0xFFFFu) ? LDCG16(&g_rank_scores[wv])
                                     : LDCG16(&g_rank_prior[gtid]);
            g_psr[gtid] = pr;
            atomicAdd(&g_hist[pr], 1u);
        }
        if (gtid < T) {
            u16 it = LDCG16(&g_si[gtid]);
            g_sr[gtid] = LDCG16(&g_rank_scores[it]);
        }
    }
    gridbar();

    // ---- ph8a: psBelow partials (160/block) + chunk sorts (blocks 0..63) ----
    u32 h8 = 0, incl8 = 0;
    {
        if (tid < 160) h8 = LDCG32(&g_hist[b * 160 + tid]);
        incl8 = blockScanIncl<160>(h8, tid, lane, w, wtot);
        if (tid == 0) g_ppart[b] = wtot[0] + wtot[1] + wtot[2] + wtot[3] + wtot[4];
        __syncthreads();
    }
    if (b < 64) {
        int T = LDCGI(&g_T);
        if (tid < 256) {
            int i = (b << 8) + tid;
            chunkbuf[tid] = (i < T) ? LDCG16(&g_sr[i]) : (u16)0xFFFFu;
        }
        __syncthreads();
        for (int k = 2; k <= 256; k <<= 1) {
            for (int j = k >> 1; j > 0; j >>= 1) {
                if (tid < 256) {
                    int p = tid ^ j;
                    if (p > tid) {
                        u16 x = chunkbuf[tid], y = chunkbuf[p];
                        bool up = ((tid & k) == 0);
                        if (up ? (x > y) : (x < y)) { chunkbuf[tid] = y; chunkbuf[p] = x; }
                    }
                }
                __syncthreads();
            }
        }
        if (tid < 256) g_chunkS[(b << 8) + tid] = chunkbuf[tid];
    }
    gridbar();

    // ---- ph8b: block0 scans g_ppart -> g_poff ----
    if (b == 0) {
        u32 hP = (tid < 128) ? LDCG32(&g_ppart[tid]) : 0u;
        u32 inclP = blockScanIncl<128>(hP, tid, lane, w, wtot);
        if (tid < 128) g_poff[tid] = inclP - hP;
    }
    gridbar();

    // ---- ph8c: psBelow -> g_cursor (kernel end = final sync) ----
    if (tid < 160) {
        u32 off = LDCG32(&g_poff[b]);
        g_cursor[b * 160 + tid] = off + (incl8 - h8);
    }
}

// ---------------------------------------------------------------------------
// k_count: grid-wide dominance counts. One warp per stream item. (verified)
// ---------------------------------------------------------------------------
__global__ __launch_bounds__(256, 8)
void k_count() {
    const int T = g_T;
    if (T <= 0) return;
    const int lane = threadIdx.x & 31;
    const int warpsTotal = (gridDim.x * blockDim.x) >> 5;
    const int gw = ((blockIdx.x * blockDim.x + threadIdx.x) >> 5);

    for (int q = gw; q < T; q += warpsTotal) {
        const u16 r = g_sr[q];
        const int c0 = q >> 8;
        u32 cnt = 0;
        for (int ch = lane; ch < c0; ch += 32) {
            const u16* a = g_chunkS + (ch << 8);
            int lo = 0, hi = 256;
            while (lo < hi) { int m = (lo + hi) >> 1; if (a[m] < r) lo = m + 1; else hi = m; }
            cnt += (u32)lo;
        }
        for (int j = (q & ~255) + lane; j < q; j += 32)
            cnt += (g_sr[j] < r) ? 1u : 0u;
        #pragma unroll
        for (int o = 16; o; o >>= 1) cnt += __shfl_down_sync(0xFFFFFFFFu, cnt, o);
        if (lane == 0) g_Bq[q] = cnt;
    }
}

// ---------------------------------------------------------------------------
// k_resolve (single block): FUSED accept + resolve + epilogue. (verified)
// ---------------------------------------------------------------------------
__global__ __launch_bounds__(1024, 1)
void k_resolve(const float* __restrict__ scores,
               const float* __restrict__ priorities,
               float* __restrict__ out,
               int P, int D, long long out_size) {
    extern __shared__ u32 S[];
    u32* gU  = S;                          // RMAX
    u32* par = S + RMAX;                   // NMAX
    u16* wr  = (u16*)(S + RMAX + NMAX);    // PMAX
    __shared__ int wsum[32];
    __shared__ int sh_changed, sh_anyTies, sh_A;

    const int tid = threadIdx.x;
    const int nthr = blockDim.x;
    const int lane = tid & 31, wid = tid >> 5;
    const int T = g_T;

    // ---- accept phase ----
    {
        int myCnt = 0;
        u32 amask = 0;
        const int q0 = tid * 16;
        u16 rs[16];
        #pragma unroll
        for (int j = 0; j < 16; ++j) {
            int q = q0 + j;
            if (q < T) {
                u16 r = g_sr[q];
                rs[j] = r;
                int b = (int)g_Bq[q];
                int psb = (int)g_cursor[r];
                if (psb + b >= q + 1) { amask |= (1u << j); myCnt++; }
            }
        }
        int vv = myCnt;
        #pragma unroll
        for (int o = 1; o < 32; o <<= 1) {
            int t = __shfl_up_sync(0xFFFFFFFFu, vv, o);
            if (lane >= o) vv += t;
        }
        if (lane == 31) wsum[wid] = vv;
        __syncthreads();
        if (wid == 0) {
            int w = wsum[lane];
            #pragma unroll
            for (int o = 1; o < 32; o <<= 1) {
                int t = __shfl_up_sync(0xFFFFFFFFu, w, o);
                if (lane >= o) w += t;
            }
            wsum[lane] = w;
        }
        __syncthreads();
        int jbase = (vv - myCnt) + ((wid > 0) ? wsum[wid - 1] : 0);
        if (tid == 0) sh_A = wsum[(nthr >> 5) - 1];
        #pragma unroll
        for (int j = 0; j < 16; ++j) {
            if (amask & (1u << j)) {
                int q = q0 + j;
                g_bdata[jbase++] = ((u32)rs[j] << 14) | (u32)g_si[q];
            }
        }
        __syncthreads();
    }
    const int A = sh_A;

    for (int i = tid; i < PMAX; i += nthr) wr[i] = (i < P) ? g_writer[i] : (u16)0xFFFFu;
    __syncthreads();

    if (A > 0) {
        const int UN = P + A;

        for (int j = tid; j < A; j += nthr) atomicAdd(&g_hist[g_bdata[j] >> 14], 1u);
        __syncthreads();
        {   // exclusive prefix over RMAX -> g_cursor (U cursors)
            const int CPT = RMAX / 1024;
            const int base = tid * CPT;
            u32 s = 0;
            #pragma unroll
            for (int j = 0; j < CPT; ++j) s += g_hist[base + j];
            u32 vv = s;
            #pragma unroll
            for (int o = 1; o < 32; o <<= 1) {
                u32 t = __shfl_up_sync(0xFFFFFFFFu, vv, o);
                if (lane >= o) vv += t;
            }
            if (lane == 31) wsum[wid] = (int)vv;
            __syncthreads();
            if (wid == 0) {
                u32 w = (u32)wsum[lane];
                #pragma unroll
                for (int o = 1; o < 32; o <<= 1) {
                    u32 t = __shfl_up_sync(0xFFFFFFFFu, w, o);
                    if (lane >= o) w += t;
                }
                wsum[lane] = (int)w;
            }
            __syncthreads();
            u32 run = (vv - s) + ((wid > 0) ? (u32)wsum[wid - 1] : 0u);
            #pragma unroll
            for (int j = 0; j < CPT; ++j) {
                u32 h = g_hist[base + j];
                g_cursor[base + j] = run;
                run += h;
            }
            __syncthreads();
        }
        for (int i = tid; i < P; i += nthr) {
            u32 r = (u32)g_psr[i];
            u32 pos = atomicAdd(&g_cursor[r], 1u);
            gU[pos] = (r << 17) | (u32)i;
        }
        for (int j = tid; j < A; j += nthr) {
            u32 r = g_bdata[j] >> 14;
            u32 pos = atomicAdd(&g_cursor[r], 1u);
            gU[pos] = (r << 17) | 0x10000u | (u32)j;
        }
        __syncthreads();

        if (tid == 0) sh_anyTies = 0;
        __syncthreads();
        for (int p = tid; p + 1 < UN; p += nthr)
            if ((gU[p] >> 17) == (gU[p + 1] >> 17)) sh_anyTies = 1;
        __syncthreads();

        const int MAXIT = 32;
        for (int it = 0; it < MAXIT; ++it) {
            for (int j = tid; j < A; j += nthr) {
                u32 e = gU[j];
                par[j] = (e & 0x10000u) ? (e & 0xFFFFu) : (0x80000000u | (e & 0xFFFFu));
            }
            __syncthreads();
            for (int rd = 0; rd < 15; ++rd) {
                if (tid == 0) sh_changed = 0;
                __syncthreads();
                for (int j = tid; j < A; j += nthr) {
                    u32 pv = par[j];
                    if (!(pv & 0x80000000u)) {
                        u32 g = par[pv];
                        par[j] = g;
                        if (!(g & 0x80000000u)) sh_changed = 1;
                    }
                }
                __syncthreads();
                if (!sh_changed) break;
            }
            if (!sh_anyTies) break;
            if (it == MAXIT - 1) break;
            if (tid == 0) sh_changed = 0;
            __syncthreads();
            for (int p = tid; p < UN; p += nthr) {
                u32 r = gU[p] >> 17;
                bool leader = (p == 0) || ((gU[p - 1] >> 17) != r);
                if (leader && p + 1 < UN && (gU[p + 1] >> 17) == r) {
                    int len = 1;
                    while (p + len < UN && (gU[p + len] >> 17) == r) len++;
                    bool ch = false;
                    for (int a = 1; a < len; ++a) {
                        u32 x = gU[p + a];
                        u32 sx = (x & 0x10000u) ? (par[x & 0xFFFFu] & 0xFFFFu) : (x & 0xFFFFu);
                        u32 kx = (sx << 1) | ((x >> 16) & 1u);
                        int b = a;
                        while (b > 0) {
                            u32 y = gU[p + b - 1];
                            u32 sy = (y & 0x10000u) ? (par[y & 0xFFFFu] & 0xFFFFu) : (y & 0xFFFFu);
                            u32 ky = (sy << 1) | ((y >> 16) & 1u);
                            if (ky <= kx) break;
                            gU[p + b] = y; b--; ch = true;
                        }
                        gU[p + b] = x;
                    }
                    if (ch) sh_changed = 1;
                }
            }
            __syncthreads();
            if (!sh_changed) break;
        }

        for (int pos = A + tid; pos < UN; pos += nthr) {
            u32 e = gU[pos];
            if (e & 0x10000u) {
                u32 j = e & 0xFFFFu;
                u32 s = par[j] & 0xFFFFu;
                if (s < (u32)P) wr[s] = (u16)(g_bdata[j] & 0x3FFFu);
            }
        }
        __syncthreads();
    }

    const long long obase = (long long)P * (long long)D;
    for (int i = tid; i < P; i += nthr) {
        u16 w = wr[i];
        g_writer[i] = w;
        if (obase + i < out_size)
            out[obase + i] = (w != 0xFFFFu) ? scores[w] : priorities[i];
    }
    if (tid == 0 && obase + P < out_size)
        out[obase + P] = (float)g_fc;
}

// ---------------------------------------------------------------------------
// Row gather: one block per pool slot. (verified)
// ---------------------------------------------------------------------------
__global__ void k_copy(const float* __restrict__ pool,
                       const float* __restrict__ summaries,
                       float* __restrict__ out, int D) {
    const int row = blockIdx.x;
    const u16 w = g_writer[row];
    const float* src = (w == 0xFFFFu) ? (pool + (long long)row * D)
                                      : (summaries + (long long)w * D);
    float* dst = out + (long long)row * D;
    if ((D & 3) == 0) {
        const float4* s4 = (const float4*)src;
        float4* d4 = (float4*)dst;
        for (int i = threadIdx.x; i < (D >> 2); i += blockDim.x) d4[i] = s4[i];
    } else {
        for (int i = threadIdx.x; i < D; i += blockDim.x) dst[i] = src[i];
    }
}

// ---------------------------------------------------------------------------
// Inputs (metadata order): summaries[N,D] f32, scores[N] f32, pool[P,D] f32,
// priorities[P] f32, count i32 scalar.
// Output: concat(pool_out[P*D], priorities[P], count) as f32.
// ---------------------------------------------------------------------------
extern "C" void kernel_launch(void* const* d_in, const int* in_sizes, int n_in,
                              void* d_out, int out_size) {
    const float* summaries  = (const float*)d_in[0];
    const float* scores     = (const float*)d_in[1];
    const float* pool       = (const float*)d_in[2];
    const float* priorities = (const float*)d_in[3];
    const int*   countp     = (const int*)d_in[4];

    const int N = in_sizes[1];
    const int P = in_sizes[3];
    const int D = (N > 0) ? (in_sizes[0] / N) : 0;
    float* out = (float*)d_out;

    const int res_smem = (RMAX + NMAX) * 4 + PMAX * 2;   // 155,648
    cudaFuncSetAttribute(k_resolve, cudaFuncAttributeMaxDynamicSharedMemorySize, res_smem);

    k_front  <<<G_BLOCKS, B_THREADS>>>(scores, priorities, countp, N, P);
    k_count  <<<512, 256>>>();
    k_resolve<<<1, 1024, res_smem>>>(scores, priorities, out, P, D, (long long)out_size);
    k_copy   <<<P, 256>>>(pool, summaries, out, D);
}